// round 15
// baseline (speedup 1.0000x reference)
#include <cuda_runtime.h>
#include <cuda_bf16.h>
#include <cuda_fp16.h>
#include <cstdint>

typedef unsigned long long ull;
typedef unsigned int u32;

#define BATCH 2
#define CDIM 48
#define QC 144
#define HWD 512
#define HW (HWD*HWD)          // 262144
#define HEADS 8
#define NBH 16
#define NBF 96
#define NPIX 16384            // 128*128

// ---------------- scratch ----------------
__device__ __align__(128) __half g_q1[BATCH*QC*HW];             // pw output fp16
__device__ __align__(128) __half g_qkv16[NBH*3*NBF*NPIX];       // dw out q,k,v fp16 blocks
__device__ __align__(128) float  g_gram[NBH*NBF*NBF];
__device__ __align__(128) float  g_ssq[NBH*2*NBF];
__device__ __align__(128) float  g_attn[NBH*NBF*NBF];
__device__ __align__(128) __half g_pre16[NBH*NBF*NPIX];         // attn@v fp16, proj layout

// ---------------- helpers ----------------
__device__ __forceinline__ ull fma2(ull a, ull b, ull c) {
    ull d; asm("fma.rn.f32x2 %0,%1,%2,%3;" : "=l"(d) : "l"(a), "l"(b), "l"(c)); return d;
}
__device__ __forceinline__ ull pack2(float lo, float hi) {
    ull r; asm("mov.b64 %0,{%1,%2};" : "=l"(r) : "f"(lo), "f"(hi)); return r;
}
__device__ __forceinline__ float2 unpack2(ull v) {
    float2 r; asm("mov.b64 {%0,%1},%2;" : "=f"(r.x), "=f"(r.y) : "l"(v)); return r;
}
__device__ __forceinline__ u32 smem_u32(const void* p) {
    u32 a; asm("{ .reg .u64 t; cvta.to.shared.u64 t, %1; cvt.u32.u64 %0, t; }" : "=r"(a) : "l"(p));
    return a;
}
__device__ __forceinline__ void cp_async8(u32 dst, const void* src) {
    asm volatile("cp.async.ca.shared.global [%0], [%1], 8;" :: "r"(dst), "l"(src));
}
__device__ __forceinline__ void cp_async16(u32 dst, const void* src) {
    asm volatile("cp.async.cg.shared.global [%0], [%1], 16;" :: "r"(dst), "l"(src));
}
__device__ __forceinline__ void cp_commit() { asm volatile("cp.async.commit_group;"); }
__device__ __forceinline__ void cp_wait1() { asm volatile("cp.async.wait_group 1;"); }
__device__ __forceinline__ void cp_wait0() { asm volatile("cp.async.wait_group 0;"); }
// split ull (4 halves) into two packed-f32 ulls
__device__ __forceinline__ void h4_to_f2x2(ull h4, ull& lo, ull& hi) {
    u32 a, b;
    asm("mov.b64 {%0,%1}, %2;" : "=r"(a), "=r"(b) : "l"(h4));
    __half2 ha = *(__half2*)&a, hb = *(__half2*)&b;
    float2 fa = __half22float2(ha), fb = __half22float2(hb);
    lo = pack2(fa.x, fa.y);
    hi = pack2(fb.x, fb.y);
}

// ---------------- K0: zero accumulators ----------------
__global__ void k_zero() {
    int i = blockIdx.x * 256 + threadIdx.x;
    if (i < NBH*NBF*NBF) g_gram[i] = 0.f;
    if (i < NBH*2*NBF)   g_ssq[i]  = 0.f;
}

// ---------------- K1: 1x1 conv 48->144, 256-px tile, fp16 out ----------------
#define PW_SMEM (48*48*8 + 48*260*4)   // 68352
__global__ __launch_bounds__(256) void k_pw(const float* __restrict__ x,
                                            const float* __restrict__ w) {
    extern __shared__ char spw[];
    ull*   ws = (ull*)spw;                      // {w,w} [ic][oc]
    float* xs = (float*)(spw + 48*48*8);        // [48][260]
    int tid = threadIdx.x;
    int tx = tid & 31, ty = tid >> 5;
    int b = blockIdx.y;
    int px0 = blockIdx.x * 256;
    const float* xb = x + (size_t)b * CDIM * HW + px0;
    __half* ob = g_q1 + (size_t)b * QC * HW + px0;
    u32 xs_u = smem_u32(xs);

    for (int e = tid; e < 48*64; e += 256) {
        int ic = e >> 6, p4 = (e & 63) * 4;
        cp_async16(xs_u + (u32)(ic*260 + p4) * 4, xb + (size_t)ic * HW + p4);
    }
    cp_commit();

    for (int g = 0; g < 3; g++) {
        if (g) __syncthreads();
        for (int e = tid; e < 48*48; e += 256) {
            int oc = e / 48, ic = e % 48;
            float v = w[g*2304 + e];
            ws[ic*48 + oc] = pack2(v, v);
        }
        if (g == 0) cp_wait0();
        __syncthreads();
        ull acc[6][4];
        #pragma unroll
        for (int i = 0; i < 6; i++)
            #pragma unroll
            for (int u = 0; u < 4; u++) acc[i][u] = 0ull;
        #pragma unroll 4
        for (int ic = 0; ic < 48; ic++) {
            float4 xa = *(const float4*)&xs[ic*260 + 4*tx];
            float4 xc = *(const float4*)&xs[ic*260 + 128 + 4*tx];
            ull a0 = pack2(xa.x, xa.y), a1 = pack2(xa.z, xa.w);
            ull a2 = pack2(xc.x, xc.y), a3 = pack2(xc.z, xc.w);
            #pragma unroll
            for (int i = 0; i < 6; i++) {
                ull wv = ws[ic*48 + ty*6 + i];
                acc[i][0] = fma2(wv, a0, acc[i][0]);
                acc[i][1] = fma2(wv, a1, acc[i][1]);
                acc[i][2] = fma2(wv, a2, acc[i][2]);
                acc[i][3] = fma2(wv, a3, acc[i][3]);
            }
        }
        #pragma unroll
        for (int i = 0; i < 6; i++) {
            __half* o = ob + (size_t)(g*48 + ty*6 + i) * HW;
            float2 f0 = unpack2(acc[i][0]), f1 = unpack2(acc[i][1]);
            float2 f2 = unpack2(acc[i][2]), f3 = unpack2(acc[i][3]);
            __half2 h0 = __floats2half2_rn(f0.x, f0.y), h1 = __floats2half2_rn(f1.x, f1.y);
            __half2 h2 = __floats2half2_rn(f2.x, f2.y), h3 = __floats2half2_rn(f3.x, f3.y);
            uint2 u01; u01.x = *(u32*)&h0; u01.y = *(u32*)&h1;
            uint2 u23; u23.x = *(u32*)&h2; u23.y = *(u32*)&h3;
            *(uint2*)&o[4*tx]       = u01;
            *(uint2*)&o[128 + 4*tx] = u23;
        }
    }
}

// ---------------- K2: depthwise 3x3 (fp16 in, fp16 blocks out) + ssq ----------------
__global__ __launch_bounds__(256) void k_dw(const float* __restrict__ dww) {
    __shared__ __align__(16) float in_s[10*512];
    __shared__ __align__(16) float out_s[8*512];
    int blk = blockIdx.x;
    int hs = blk & 63;
    int bc = blk >> 6;
    int ch = bc % QC, b = bc / QC;
    int qk = ch / 48, c48 = ch % 48, head = c48 / 6, ci = c48 % 6;
    int bhi = b*HEADS + head;
    int tid = threadIdx.x;
    const __half* base = g_q1 + (size_t)bc * HW;
    float wt[9];
    #pragma unroll
    for (int k = 0; k < 9; k++) wt[k] = __ldg(&dww[ch*9 + k]);
    int h0 = hs * 8;

    for (int e = tid; e < 2560; e += 256) {
        int rr = e >> 8, c2 = (e & 255) * 2;
        int hh = h0 - 1 + rr;
        float2 f;
        if (hh >= 0 && hh < 512) {
            __half2 hv = *(const __half2*)(base + (size_t)hh*512 + c2);
            f = __half22float2(hv);
        } else { f.x = 0.f; f.y = 0.f; }
        *(float2*)&in_s[rr*512 + c2] = f;
    }
    __syncthreads();

    int w = tid * 2;
    float lsq[4][2] = {{0.f,0.f},{0.f,0.f},{0.f,0.f},{0.f,0.f}};
    #pragma unroll
    for (int r = 0; r < 8; r++) {
        float a0 = 0.f, a1 = 0.f;
        #pragma unroll
        for (int dy = 0; dy < 3; dy++) {
            const float* row = &in_s[(r + dy) * 512];
            float vm = (w > 0)   ? row[w-1] : 0.f;
            float v0 = row[w];
            float v1 = row[w+1];
            float v2 = (w < 510) ? row[w+2] : 0.f;
            a0 += wt[dy*3+0]*vm + wt[dy*3+1]*v0 + wt[dy*3+2]*v1;
            a1 += wt[dy*3+0]*v0 + wt[dy*3+1]*v1 + wt[dy*3+2]*v2;
        }
        *(ull*)&out_s[r*512 + w] = pack2(a0, a1);
        if (qk < 2) { int nh = r & 3; lsq[nh][0] += a0*a0; lsq[nh][1] += a1*a1; }
    }
    __syncthreads();

    __half* dstbase = g_qkv16 + (size_t)(bhi*3 + qk) * NBF * NPIX;
    for (int e = tid; e < 2048; e += 256) {
        int r = e >> 8, nw = (e >> 6) & 3, ip = (e & 63) * 2;
        float f0 = out_s[r*512 + ip*4 + nw];
        float f1 = out_s[r*512 + (ip+1)*4 + nw];
        int f = (ci*4 + (r & 3))*4 + nw;
        int s = (hs*2 + (r >> 2))*128 + ip;
        *(__half2*)&dstbase[(size_t)f * NPIX + s] = __floats2half2_rn(f0, f1);
    }

    if (qk < 2) {
        #pragma unroll
        for (int off = 2; off < 32; off <<= 1)
            #pragma unroll
            for (int nh = 0; nh < 4; nh++) {
                lsq[nh][0] += __shfl_xor_sync(0xffffffffu, lsq[nh][0], off);
                lsq[nh][1] += __shfl_xor_sync(0xffffffffu, lsq[nh][1], off);
            }
        int lane = tid & 31;
        if (lane < 2) {
            float* d = &g_ssq[(bhi*2 + qk)*NBF + ci*16];
            #pragma unroll
            for (int nh = 0; nh < 4; nh++) {
                atomicAdd(&d[nh*4 + lane*2 + 0], lsq[nh][0]);
                atomicAdd(&d[nh*4 + lane*2 + 1], lsq[nh][1]);
            }
        }
    }
}

// ---------------- K3: partial Gram, fp16 feed, cp.async double-buffered ----------------
#define GPH 68                 // halves pitch (136B rows: 8B aligned, k-loads conflict-free)
#define GSTGH (96*GPH)         // halves per stage per array
#define GRAM_SMEM (4*GSTGH*2)  // 52224 B
__global__ __launch_bounds__(256, 2) void k_gram() {
    extern __shared__ __half smh[];
    __half* qs = smh;                 // [2][96][GPH]
    __half* ks = smh + 2*GSTGH;
    int tid = threadIdx.x;
    int ty = tid >> 4, tx = tid & 15;
    int bh = blockIdx.y;
    int chunk = blockIdx.x;
    const __half* qb = g_qkv16 + (size_t)bh * 3 * NBF * NPIX;
    const __half* kb = qb + (size_t)NBF * NPIX;
    u32 qs_u = smem_u32(qs);
    u32 ks_u = smem_u32(ks);

    ull acc[6][6];
    #pragma unroll
    for (int i = 0; i < 6; i++)
        #pragma unroll
        for (int j = 0; j < 6; j++) acc[i][j] = 0ull;

    auto stage_copy = [&](int stg, int sub) {
        int s0 = chunk * 512 + sub * 64;
        for (int e = tid; e < 96*16; e += 256) {       // 16 8B-chunks per 128B row
            int r = e >> 4, c4 = (e & 15) * 4;
            u32 off = (u32)(stg*GSTGH + r*GPH + c4) * 2;
            cp_async8(qs_u + off, qb + (size_t)r * NPIX + s0 + c4);
            cp_async8(ks_u + off, kb + (size_t)r * NPIX + s0 + c4);
        }
        cp_commit();
    };

    stage_copy(0, 0);
    stage_copy(1, 1);
    for (int sub = 0; sub < 8; sub++) {
        int cur = sub & 1;
        if (sub < 7) cp_wait1(); else cp_wait0();
        __syncthreads();
        const __half* q = qs + cur * GSTGH;
        const __half* k = ks + cur * GSTGH;
        #pragma unroll 4
        for (int c = 0; c < 64; c += 4) {
            ull qlo[6], qhi[6], klo[6], khi[6];
            #pragma unroll
            for (int i = 0; i < 6; i++) {
                ull h4 = *(const ull*)&q[(i*16 + ty)*GPH + c];
                h4_to_f2x2(h4, qlo[i], qhi[i]);
            }
            #pragma unroll
            for (int j = 0; j < 6; j++) {
                ull h4 = *(const ull*)&k[(j*16 + tx)*GPH + c];
                h4_to_f2x2(h4, klo[j], khi[j]);
            }
            #pragma unroll
            for (int i = 0; i < 6; i++)
                #pragma unroll
                for (int j = 0; j < 6; j++) {
                    acc[i][j] = fma2(qlo[i], klo[j], acc[i][j]);
                    acc[i][j] = fma2(qhi[i], khi[j], acc[i][j]);
                }
        }
        __syncthreads();
        if (sub + 2 < 8) stage_copy(cur, sub + 2);
    }
    #pragma unroll
    for (int i = 0; i < 6; i++)
        #pragma unroll
        for (int j = 0; j < 6; j++) {
            float2 u = unpack2(acc[i][j]);
            atomicAdd(&g_gram[(bh*NBF + i*16 + ty)*NBF + j*16 + tx], u.x + u.y);
        }
}

// ---------------- K4: softmax ----------------
__global__ __launch_bounds__(256) void k_soft(const float* __restrict__ temp) {
    int wid = threadIdx.x >> 5, lane = threadIdx.x & 31;
    int rid = blockIdx.x * 8 + wid;
    int bh = rid / NBF, i = rid % NBF;
    int head = bh & 7;
    const float* ss = g_ssq + bh * 2 * NBF;
    float nq = fmaxf(sqrtf(ss[i]), 1e-12f);
    float t = temp[head];
    float v[3];
    #pragma unroll
    for (int u = 0; u < 3; u++) {
        int j = lane + 32*u;
        float nk = fmaxf(sqrtf(ss[NBF + j]), 1e-12f);
        v[u] = g_gram[(bh*NBF + i)*NBF + j] / (nq * nk) * t;
    }
    float m = fmaxf(v[0], fmaxf(v[1], v[2]));
    #pragma unroll
    for (int off = 16; off; off >>= 1) m = fmaxf(m, __shfl_xor_sync(0xffffffffu, m, off));
    float s = 0.f;
    #pragma unroll
    for (int u = 0; u < 3; u++) { v[u] = expf(v[u] - m); s += v[u]; }
    #pragma unroll
    for (int off = 16; off; off >>= 1) s += __shfl_xor_sync(0xffffffffu, s, off);
    float inv = 1.f / s;
    #pragma unroll
    for (int u = 0; u < 3; u++)
        g_attn[(bh*NBF + i)*NBF + lane + 32*u] = v[u] * inv;
}

// ---------------- K5: attn@v (fp16 v feed), prepacked attn, fp16 output ----------------
#define PVH 132                     // halves pitch for v tiles
#define PVS (16*PVH)                // halves per stage
#define AV_SMEM (96*96*8 + 2*PVS*2) // 73728 + 8448 = 82176
__global__ __launch_bounds__(256, 2) void k_av() {
    extern __shared__ char sma[];
    ull*    att  = (ull*)sma;                   // [96][96] packed {a,a}
    __half* vs   = (__half*)(sma + 96*96*8);    // [2][16][PVH]
    float*  outs = (float*)sma;                 // [96][130] overlay (post-compute)
    int tid = threadIdx.x;
    int ty = tid >> 4, tx = tid & 15;
    int bh = blockIdx.y;
    int px0 = blockIdx.x * 128;
    const __half* vb = g_qkv16 + (size_t)(bh*3 + 2) * NBF * NPIX;
    u32 vs_u = smem_u32(vs);

    for (int e = tid; e < 96*96; e += 256) {
        float a = g_attn[bh*NBF*NBF + e];
        att[e] = pack2(a, a);
    }

    ull acc[6][4];
    #pragma unroll
    for (int i = 0; i < 6; i++)
        #pragma unroll
        for (int u = 0; u < 4; u++) acc[i][u] = 0ull;

    auto vcopy = [&](int stg, int jt) {
        for (int e = tid; e < 512; e += 256) {     // 16 rows x 32 8B-chunks
            int jc = e >> 5, ch = e & 31;
            u32 off = (u32)(stg*PVS + jc*PVH + ch*4) * 2;
            cp_async8(vs_u + off, vb + (size_t)(jt*16 + jc) * NPIX + px0 + ch*4);
        }
        cp_commit();
    };

    vcopy(0, 0);
    __syncthreads();
    for (int jt = 0; jt < 6; jt++) {
        int cur = jt & 1;
        if (jt < 5) { vcopy(cur ^ 1, jt + 1); cp_wait1(); }
        else        { cp_wait0(); }
        __syncthreads();
        const __half* vloc = vs + cur * PVS;
        #pragma unroll 2
        for (int jc = 0; jc < 16; jc++) {
            ull vv[4];
            #pragma unroll
            for (int u = 0; u < 4; u++) {
                __half2 hv = *(const __half2*)&vloc[jc*PVH + u*32 + 2*tx];
                float2 f = __half22float2(hv);
                vv[u] = pack2(f.x, f.y);
            }
            #pragma unroll
            for (int i = 0; i < 6; i++) {
                ull a2 = att[(ty*6 + i)*96 + jt*16 + jc];
                acc[i][0] = fma2(a2, vv[0], acc[i][0]);
                acc[i][1] = fma2(a2, vv[1], acc[i][1]);
                acc[i][2] = fma2(a2, vv[2], acc[i][2]);
                acc[i][3] = fma2(a2, vv[3], acc[i][3]);
            }
        }
        __syncthreads();
    }
    #pragma unroll
    for (int i = 0; i < 6; i++) {
        int row = ty*6 + i;
        #pragma unroll
        for (int u = 0; u < 4; u++)
            *(ull*)&outs[row*130 + u*32 + 2*tx] = acc[i][u];
    }
    __syncthreads();
    __half* dst = g_pre16 + (size_t)bh * 24 * NPIX * 4 + (size_t)px0 * 4;
    for (int e = tid; e < 24*256; e += 256) {
        int p = e >> 8, r = e & 255;
        int s = r >> 1, nwp = (r & 1) * 2;
        float f0 = outs[(p*4 + nwp    )*130 + s];
        float f1 = outs[(p*4 + nwp + 1)*130 + s];
        *(__half2*)&dst[(size_t)p * NPIX * 4 + s*4 + nwp] = __floats2half2_rn(f0, f1);
    }
}

// ---------------- K6: 1x1 proj (fp16 in), 256-px tile -> d_out ----------------
#define PROJ_SMEM (48*48*8 + 48*260*4)   // 68352
__global__ __launch_bounds__(256) void k_proj(const float* __restrict__ pw,
                                              float* __restrict__ out) {
    extern __shared__ char spj[];
    ull*   w2s  = (ull*)spj;
    float* in_s = (float*)(spj + 48*48*8);      // [48][260]
    int tid = threadIdx.x + threadIdx.y * 32;
    int tx = threadIdx.x, ty = threadIdx.y;
    int wb = blockIdx.x * 256;
    int h = blockIdx.y;
    int b = blockIdx.z;
    int nh = h & 3;
    int soff = ((h >> 2) * 128 + (wb >> 2)) * 4;

    for (int e = tid; e < 2304; e += 256) {
        int oc = e / 48, ic = e % 48;
        float v = pw[e];
        w2s[ic*48 + oc] = pack2(v, v);
    }
    for (int e = tid; e < 48*128; e += 256) {
        int ic = e >> 7, p2 = (e & 127) * 2;
        int head = ic / 6, ci = ic % 6;
        int p = ci*4 + nh;
        const __half* src = g_pre16 +
            ((size_t)(b*HEADS + head)*24 + p) * NPIX * 4 + soff + p2;
        float2 f = __half22float2(*(const __half2*)src);
        *(float2*)&in_s[ic*260 + p2] = f;
    }
    __syncthreads();

    ull acc[6][4];
    #pragma unroll
    for (int i = 0; i < 6; i++)
        #pragma unroll
        for (int u = 0; u < 4; u++) acc[i][u] = 0ull;
    #pragma unroll 4
    for (int ic = 0; ic < 48; ic++) {
        float4 xa = *(const float4*)&in_s[ic*260 + 4*tx];
        float4 xc = *(const float4*)&in_s[ic*260 + 128 + 4*tx];
        ull a0 = pack2(xa.x, xa.y), a1 = pack2(xa.z, xa.w);
        ull a2 = pack2(xc.x, xc.y), a3 = pack2(xc.z, xc.w);
        #pragma unroll
        for (int i = 0; i < 6; i++) {
            ull wv = w2s[ic*48 + ty*6 + i];
            acc[i][0] = fma2(wv, a0, acc[i][0]);
            acc[i][1] = fma2(wv, a1, acc[i][1]);
            acc[i][2] = fma2(wv, a2, acc[i][2]);
            acc[i][3] = fma2(wv, a3, acc[i][3]);
        }
    }
    #pragma unroll
    for (int i = 0; i < 6; i++) {
        int oc = ty*6 + i;
        float* ob = out + ((size_t)(b*CDIM + oc)*512 + h)*512 + wb;
        float2 f0 = unpack2(acc[i][0]), f1 = unpack2(acc[i][1]);
        float2 f2 = unpack2(acc[i][2]), f3 = unpack2(acc[i][3]);
        float4 o0; o0.x = f0.x; o0.y = f0.y; o0.z = f1.x; o0.w = f1.y;
        float4 o1; o1.x = f2.x; o1.y = f2.y; o1.z = f3.x; o1.w = f3.y;
        *(float4*)&ob[4*tx]       = o0;
        *(float4*)&ob[128 + 4*tx] = o1;
    }
}

extern "C" void kernel_launch(void* const* d_in, const int* in_sizes, int n_in,
                              void* d_out, int out_size) {
    const float* x     = (const float*)d_in[0];
    const float* qkvw  = (const float*)d_in[1];
    const float* dww   = (const float*)d_in[2];
    const float* projw = (const float*)d_in[3];
    const float* temp  = (const float*)d_in[4];
    float* out = (float*)d_out;

    cudaFuncSetAttribute(k_pw,   cudaFuncAttributeMaxDynamicSharedMemorySize, PW_SMEM);
    cudaFuncSetAttribute(k_gram, cudaFuncAttributeMaxDynamicSharedMemorySize, GRAM_SMEM);
    cudaFuncSetAttribute(k_av,   cudaFuncAttributeMaxDynamicSharedMemorySize, AV_SMEM);
    cudaFuncSetAttribute(k_proj, cudaFuncAttributeMaxDynamicSharedMemorySize, PROJ_SMEM);

    k_zero<<<576, 256>>>();
    k_pw  <<<dim3(HW/256, BATCH), 256, PW_SMEM>>>(x, qkvw);
    k_dw  <<<BATCH*QC*64, 256>>>(dww);
    k_gram<<<dim3(32, NBH), 256, GRAM_SMEM>>>();
    k_soft<<<192, 256>>>(temp);
    k_av  <<<dim3(NPIX/128, NBH), 256, AV_SMEM>>>();
    k_proj<<<dim3(2, 512, BATCH), dim3(32, 8), PROJ_SMEM>>>(projw, out);
}

// round 16
// speedup vs baseline: 1.0286x; 1.0286x over previous
#include <cuda_runtime.h>
#include <cuda_bf16.h>
#include <cuda_fp16.h>
#include <cstdint>

typedef unsigned long long ull;
typedef unsigned int u32;

#define BATCH 2
#define CDIM 48
#define QC 144
#define HWD 512
#define HW (HWD*HWD)          // 262144
#define HEADS 8
#define NBH 16
#define NBF 96
#define NPIX 16384            // 128*128

// ---------------- scratch ----------------
__device__ __align__(128) __half g_q1[BATCH*QC*HW];             // pw output fp16
__device__ __align__(128) __half g_qkv16[NBH*3*NBF*NPIX];       // dw out q,k,v fp16 blocks
__device__ __align__(128) float  g_gram[NBH*NBF*NBF];
__device__ __align__(128) float  g_ssq[NBH*2*NBF];
__device__ __align__(128) float  g_attn[NBH*NBF*NBF];
__device__ __align__(128) __half g_pre16[NBH*NBF*NPIX];         // attn@v fp16, proj layout

// ---------------- helpers ----------------
__device__ __forceinline__ ull fma2(ull a, ull b, ull c) {
    ull d; asm("fma.rn.f32x2 %0,%1,%2,%3;" : "=l"(d) : "l"(a), "l"(b), "l"(c)); return d;
}
__device__ __forceinline__ ull pack2(float lo, float hi) {
    ull r; asm("mov.b64 %0,{%1,%2};" : "=l"(r) : "f"(lo), "f"(hi)); return r;
}
__device__ __forceinline__ float2 unpack2(ull v) {
    float2 r; asm("mov.b64 {%0,%1},%2;" : "=f"(r.x), "=f"(r.y) : "l"(v)); return r;
}
__device__ __forceinline__ u32 smem_u32(const void* p) {
    u32 a; asm("{ .reg .u64 t; cvta.to.shared.u64 t, %1; cvt.u32.u64 %0, t; }" : "=r"(a) : "l"(p));
    return a;
}
__device__ __forceinline__ void cp_async16(u32 dst, const void* src) {
    asm volatile("cp.async.cg.shared.global [%0], [%1], 16;" :: "r"(dst), "l"(src));
}
__device__ __forceinline__ void cp_commit() { asm volatile("cp.async.commit_group;"); }
__device__ __forceinline__ void cp_wait0() { asm volatile("cp.async.wait_group 0;"); }
// split ull (4 halves) into two packed-f32 ulls
__device__ __forceinline__ void h4_to_f2x2(ull h4, ull& lo, ull& hi) {
    u32 a, b;
    asm("mov.b64 {%0,%1}, %2;" : "=r"(a), "=r"(b) : "l"(h4));
    __half2 ha = *(__half2*)&a, hb = *(__half2*)&b;
    float2 fa = __half22float2(ha), fb = __half22float2(hb);
    lo = pack2(fa.x, fa.y);
    hi = pack2(fb.x, fb.y);
}

// ---------------- K0: zero accumulators ----------------
__global__ void k_zero() {
    int i = blockIdx.x * 256 + threadIdx.x;
    if (i < NBH*NBF*NBF) g_gram[i] = 0.f;
    if (i < NBH*2*NBF)   g_ssq[i]  = 0.f;
}

// ---------------- K1: 1x1 conv 48->144, 256-px tile, fp16 out ----------------
#define PW_SMEM (48*48*8 + 48*260*4)   // 68352
__global__ __launch_bounds__(256) void k_pw(const float* __restrict__ x,
                                            const float* __restrict__ w) {
    extern __shared__ char spw[];
    ull*   ws = (ull*)spw;                      // {w,w} [ic][oc]
    float* xs = (float*)(spw + 48*48*8);        // [48][260]
    int tid = threadIdx.x;
    int tx = tid & 31, ty = tid >> 5;
    int b = blockIdx.y;
    int px0 = blockIdx.x * 256;
    const float* xb = x + (size_t)b * CDIM * HW + px0;
    __half* ob = g_q1 + (size_t)b * QC * HW + px0;
    u32 xs_u = smem_u32(xs);

    for (int e = tid; e < 48*64; e += 256) {
        int ic = e >> 6, p4 = (e & 63) * 4;
        cp_async16(xs_u + (u32)(ic*260 + p4) * 4, xb + (size_t)ic * HW + p4);
    }
    cp_commit();

    for (int g = 0; g < 3; g++) {
        if (g) __syncthreads();
        for (int e = tid; e < 48*48; e += 256) {
            int oc = e / 48, ic = e % 48;
            float v = w[g*2304 + e];
            ws[ic*48 + oc] = pack2(v, v);
        }
        if (g == 0) cp_wait0();
        __syncthreads();
        ull acc[6][4];
        #pragma unroll
        for (int i = 0; i < 6; i++)
            #pragma unroll
            for (int u = 0; u < 4; u++) acc[i][u] = 0ull;
        #pragma unroll 4
        for (int ic = 0; ic < 48; ic++) {
            float4 xa = *(const float4*)&xs[ic*260 + 4*tx];
            float4 xc = *(const float4*)&xs[ic*260 + 128 + 4*tx];
            ull a0 = pack2(xa.x, xa.y), a1 = pack2(xa.z, xa.w);
            ull a2 = pack2(xc.x, xc.y), a3 = pack2(xc.z, xc.w);
            #pragma unroll
            for (int i = 0; i < 6; i++) {
                ull wv = ws[ic*48 + ty*6 + i];
                acc[i][0] = fma2(wv, a0, acc[i][0]);
                acc[i][1] = fma2(wv, a1, acc[i][1]);
                acc[i][2] = fma2(wv, a2, acc[i][2]);
                acc[i][3] = fma2(wv, a3, acc[i][3]);
            }
        }
        #pragma unroll
        for (int i = 0; i < 6; i++) {
            __half* o = ob + (size_t)(g*48 + ty*6 + i) * HW;
            float2 f0 = unpack2(acc[i][0]), f1 = unpack2(acc[i][1]);
            float2 f2 = unpack2(acc[i][2]), f3 = unpack2(acc[i][3]);
            __half2 h0 = __floats2half2_rn(f0.x, f0.y), h1 = __floats2half2_rn(f1.x, f1.y);
            __half2 h2 = __floats2half2_rn(f2.x, f2.y), h3 = __floats2half2_rn(f3.x, f3.y);
            uint2 u01; u01.x = *(u32*)&h0; u01.y = *(u32*)&h1;
            uint2 u23; u23.x = *(u32*)&h2; u23.y = *(u32*)&h3;
            *(uint2*)&o[4*tx]       = u01;
            *(uint2*)&o[128 + 4*tx] = u23;
        }
    }
}

// ---------------- K2: depthwise 3x3 (fp16 in, fp16 blocks out) + ssq ----------------
__global__ __launch_bounds__(256) void k_dw(const float* __restrict__ dww) {
    __shared__ __align__(16) float in_s[10*512];
    __shared__ __align__(16) float out_s[8*512];
    int blk = blockIdx.x;
    int hs = blk & 63;
    int bc = blk >> 6;
    int ch = bc % QC, b = bc / QC;
    int qk = ch / 48, c48 = ch % 48, head = c48 / 6, ci = c48 % 6;
    int bhi = b*HEADS + head;
    int tid = threadIdx.x;
    const __half* base = g_q1 + (size_t)bc * HW;
    float wt[9];
    #pragma unroll
    for (int k = 0; k < 9; k++) wt[k] = __ldg(&dww[ch*9 + k]);
    int h0 = hs * 8;

    for (int e = tid; e < 2560; e += 256) {
        int rr = e >> 8, c2 = (e & 255) * 2;
        int hh = h0 - 1 + rr;
        float2 f;
        if (hh >= 0 && hh < 512) {
            __half2 hv = *(const __half2*)(base + (size_t)hh*512 + c2);
            f = __half22float2(hv);
        } else { f.x = 0.f; f.y = 0.f; }
        *(float2*)&in_s[rr*512 + c2] = f;
    }
    __syncthreads();

    int w = tid * 2;
    float lsq[4][2] = {{0.f,0.f},{0.f,0.f},{0.f,0.f},{0.f,0.f}};
    #pragma unroll
    for (int r = 0; r < 8; r++) {
        float a0 = 0.f, a1 = 0.f;
        #pragma unroll
        for (int dy = 0; dy < 3; dy++) {
            const float* row = &in_s[(r + dy) * 512];
            float vm = (w > 0)   ? row[w-1] : 0.f;
            float v0 = row[w];
            float v1 = row[w+1];
            float v2 = (w < 510) ? row[w+2] : 0.f;
            a0 += wt[dy*3+0]*vm + wt[dy*3+1]*v0 + wt[dy*3+2]*v1;
            a1 += wt[dy*3+0]*v0 + wt[dy*3+1]*v1 + wt[dy*3+2]*v2;
        }
        *(ull*)&out_s[r*512 + w] = pack2(a0, a1);
        if (qk < 2) { int nh = r & 3; lsq[nh][0] += a0*a0; lsq[nh][1] += a1*a1; }
    }
    __syncthreads();

    __half* dstbase = g_qkv16 + (size_t)(bhi*3 + qk) * NBF * NPIX;
    for (int e = tid; e < 2048; e += 256) {
        int r = e >> 8, nw = (e >> 6) & 3, ip = (e & 63) * 2;
        float f0 = out_s[r*512 + ip*4 + nw];
        float f1 = out_s[r*512 + (ip+1)*4 + nw];
        int f = (ci*4 + (r & 3))*4 + nw;
        int s = (hs*2 + (r >> 2))*128 + ip;
        *(__half2*)&dstbase[(size_t)f * NPIX + s] = __floats2half2_rn(f0, f1);
    }

    if (qk < 2) {
        #pragma unroll
        for (int off = 2; off < 32; off <<= 1)
            #pragma unroll
            for (int nh = 0; nh < 4; nh++) {
                lsq[nh][0] += __shfl_xor_sync(0xffffffffu, lsq[nh][0], off);
                lsq[nh][1] += __shfl_xor_sync(0xffffffffu, lsq[nh][1], off);
            }
        int lane = tid & 31;
        if (lane < 2) {
            float* d = &g_ssq[(bhi*2 + qk)*NBF + ci*16];
            #pragma unroll
            for (int nh = 0; nh < 4; nh++) {
                atomicAdd(&d[nh*4 + lane*2 + 0], lsq[nh][0]);
                atomicAdd(&d[nh*4 + lane*2 + 1], lsq[nh][1]);
            }
        }
    }
}

// ---------------- K3: partial Gram — fp16 DRAM, fp32 smem (convert at staging),
//                  register-pipelined LDG (2 stages ahead). Inner loop == R14. ----------------
#define GPITCH 34
#define GSTG (96*GPITCH)
#define GRAM_SMEM (4*GSTG*4)   // 52224 B
__global__ __launch_bounds__(256, 2) void k_gram() {
    extern __shared__ float smg[];
    float* qs = smg;                 // [2][96][34]
    float* ks = smg + 2*GSTG;
    int tid = threadIdx.x;
    int ty = tid >> 4, tx = tid & 15;
    int bh = blockIdx.y;
    int chunk = blockIdx.x;
    const __half* qb = g_qkv16 + (size_t)bh * 3 * NBF * NPIX;
    const __half* kb = qb + (size_t)NBF * NPIX;

    ull acc[6][6];
    #pragma unroll
    for (int i = 0; i < 6; i++)
        #pragma unroll
        for (int j = 0; j < 6; j++) acc[i][j] = 0ull;

    ull qr[3], kr[3];                 // 4 halves each, staged 2 subs ahead
    auto ldg_stage = [&](int sub) {
        int s0 = chunk * 512 + sub * 32;
        #pragma unroll
        for (int c = 0; c < 3; c++) {
            int idx = c*1024 + tid*4;
            int r = idx >> 5, col = idx & 31;
            qr[c] = *(const ull*)(qb + (size_t)r * NPIX + s0 + col);
            kr[c] = *(const ull*)(kb + (size_t)r * NPIX + s0 + col);
        }
    };
    auto sts_stage = [&](int stg) {
        #pragma unroll
        for (int c = 0; c < 3; c++) {
            int idx = c*1024 + tid*4;
            int r = idx >> 5, col = idx & 31;
            ull lo, hi;
            h4_to_f2x2(qr[c], lo, hi);
            *(ull*)&qs[stg*GSTG + r*GPITCH + col]     = lo;
            *(ull*)&qs[stg*GSTG + r*GPITCH + col + 2] = hi;
            h4_to_f2x2(kr[c], lo, hi);
            *(ull*)&ks[stg*GSTG + r*GPITCH + col]     = lo;
            *(ull*)&ks[stg*GSTG + r*GPITCH + col + 2] = hi;
        }
    };

    ldg_stage(0);
    sts_stage(0);
    ldg_stage(1);
    __syncthreads();
    for (int sub = 0; sub < 16; sub++) {
        int cur = sub & 1;
        const float* q = qs + cur * GSTG;
        const float* k = ks + cur * GSTG;
        #pragma unroll
        for (int c = 0; c < 32; c += 2) {
            ull qv[6], kv[6];
            #pragma unroll
            for (int i = 0; i < 6; i++) qv[i] = *(const ull*)&q[(i*16 + ty)*GPITCH + c];
            #pragma unroll
            for (int j = 0; j < 6; j++) kv[j] = *(const ull*)&k[(j*16 + tx)*GPITCH + c];
            #pragma unroll
            for (int i = 0; i < 6; i++)
                #pragma unroll
                for (int j = 0; j < 6; j++)
                    acc[i][j] = fma2(qv[i], kv[j], acc[i][j]);
        }
        if (sub < 15) {
            sts_stage(cur ^ 1);              // data for sub+1 (already in regs)
            if (sub + 2 < 16) ldg_stage(sub + 2);
            __syncthreads();
        }
    }
    #pragma unroll
    for (int i = 0; i < 6; i++)
        #pragma unroll
        for (int j = 0; j < 6; j++) {
            float2 u = unpack2(acc[i][j]);
            atomicAdd(&g_gram[(bh*NBF + i*16 + ty)*NBF + j*16 + tx], u.x + u.y);
        }
}

// ---------------- K4: softmax ----------------
__global__ __launch_bounds__(256) void k_soft(const float* __restrict__ temp) {
    int wid = threadIdx.x >> 5, lane = threadIdx.x & 31;
    int rid = blockIdx.x * 8 + wid;
    int bh = rid / NBF, i = rid % NBF;
    int head = bh & 7;
    const float* ss = g_ssq + bh * 2 * NBF;
    float nq = fmaxf(sqrtf(ss[i]), 1e-12f);
    float t = temp[head];
    float v[3];
    #pragma unroll
    for (int u = 0; u < 3; u++) {
        int j = lane + 32*u;
        float nk = fmaxf(sqrtf(ss[NBF + j]), 1e-12f);
        v[u] = g_gram[(bh*NBF + i)*NBF + j] / (nq * nk) * t;
    }
    float m = fmaxf(v[0], fmaxf(v[1], v[2]));
    #pragma unroll
    for (int off = 16; off; off >>= 1) m = fmaxf(m, __shfl_xor_sync(0xffffffffu, m, off));
    float s = 0.f;
    #pragma unroll
    for (int u = 0; u < 3; u++) { v[u] = expf(v[u] - m); s += v[u]; }
    #pragma unroll
    for (int off = 16; off; off >>= 1) s += __shfl_xor_sync(0xffffffffu, s, off);
    float inv = 1.f / s;
    #pragma unroll
    for (int u = 0; u < 3; u++)
        g_attn[(bh*NBF + i)*NBF + lane + 32*u] = v[u] * inv;
}

// ---------------- K5: attn@v — fp16 v DRAM, fp32 smem tiles (convert at staging),
//                  register-pipelined LDG. Inner loop == R14. fp16 output. ----------------
#define PVSF (16*132)                       // floats per v stage
#define AV_SMEM (96*96*8 + 2*PVSF*4)        // 73728 + 16896 = 90624
__global__ __launch_bounds__(256, 2) void k_av() {
    extern __shared__ char sma[];
    ull*   att  = (ull*)sma;                // [96][96] packed {a,a}
    float* vs   = (float*)(sma + 96*96*8);  // [2][16][132] fp32
    float* outs = (float*)sma;              // [96][130] overlay (post-compute)
    int tid = threadIdx.x;
    int ty = tid >> 4, tx = tid & 15;
    int bh = blockIdx.y;
    int px0 = blockIdx.x * 128;
    const __half* vb = g_qkv16 + (size_t)(bh*3 + 2) * NBF * NPIX;

    ull vr[2];
    auto ldgv = [&](int jt) {
        #pragma unroll
        for (int c = 0; c < 2; c++) {
            int idx = c*1024 + tid*4;
            int jc = idx >> 7, col = idx & 127;
            vr[c] = *(const ull*)(vb + (size_t)(jt*16 + jc) * NPIX + px0 + col);
        }
    };
    auto stsv = [&](int stg) {
        #pragma unroll
        for (int c = 0; c < 2; c++) {
            int idx = c*1024 + tid*4;
            int jc = idx >> 7, col = idx & 127;
            ull lo, hi;
            h4_to_f2x2(vr[c], lo, hi);
            *(ull*)&vs[stg*PVSF + jc*132 + col]     = lo;
            *(ull*)&vs[stg*PVSF + jc*132 + col + 2] = hi;
        }
    };

    ldgv(0);
    for (int e = tid; e < 96*96; e += 256) {
        float a = g_attn[bh*NBF*NBF + e];
        att[e] = pack2(a, a);
    }
    stsv(0);
    ldgv(1);

    ull acc[6][4];
    #pragma unroll
    for (int i = 0; i < 6; i++)
        #pragma unroll
        for (int u = 0; u < 4; u++) acc[i][u] = 0ull;

    __syncthreads();
    for (int jt = 0; jt < 6; jt++) {
        int cur = jt & 1;
        const float* vloc = vs + cur * PVSF;
        #pragma unroll 2
        for (int jc = 0; jc < 16; jc++) {
            ull vv[4];
            #pragma unroll
            for (int u = 0; u < 4; u++) vv[u] = *(const ull*)&vloc[jc*132 + u*32 + 2*tx];
            #pragma unroll
            for (int i = 0; i < 6; i++) {
                ull a2 = att[(ty*6 + i)*96 + jt*16 + jc];
                acc[i][0] = fma2(a2, vv[0], acc[i][0]);
                acc[i][1] = fma2(a2, vv[1], acc[i][1]);
                acc[i][2] = fma2(a2, vv[2], acc[i][2]);
                acc[i][3] = fma2(a2, vv[3], acc[i][3]);
            }
        }
        if (jt < 5) {
            stsv(cur ^ 1);
            if (jt + 2 < 6) ldgv(jt + 2);
            __syncthreads();
        }
    }
    __syncthreads();                          // att reads done before outs overlay
    #pragma unroll
    for (int i = 0; i < 6; i++) {
        int row = ty*6 + i;
        #pragma unroll
        for (int u = 0; u < 4; u++)
            *(ull*)&outs[row*130 + u*32 + 2*tx] = acc[i][u];
    }
    __syncthreads();
    __half* dst = g_pre16 + (size_t)bh * 24 * NPIX * 4 + (size_t)px0 * 4;
    for (int e = tid; e < 24*256; e += 256) {
        int p = e >> 8, r = e & 255;
        int s = r >> 1, nwp = (r & 1) * 2;
        float f0 = outs[(p*4 + nwp    )*130 + s];
        float f1 = outs[(p*4 + nwp + 1)*130 + s];
        *(__half2*)&dst[(size_t)p * NPIX * 4 + s*4 + nwp] = __floats2half2_rn(f0, f1);
    }
}

// ---------------- K6: 1x1 proj (fp16 in), 256-px tile -> d_out ----------------
#define PROJ_SMEM (48*48*8 + 48*260*4)   // 68352
__global__ __launch_bounds__(256) void k_proj(const float* __restrict__ pw,
                                              float* __restrict__ out) {
    extern __shared__ char spj[];
    ull*   w2s  = (ull*)spj;
    float* in_s = (float*)(spj + 48*48*8);      // [48][260]
    int tid = threadIdx.x + threadIdx.y * 32;
    int tx = threadIdx.x, ty = threadIdx.y;
    int wb = blockIdx.x * 256;
    int h = blockIdx.y;
    int b = blockIdx.z;
    int nh = h & 3;
    int soff = ((h >> 2) * 128 + (wb >> 2)) * 4;

    for (int e = tid; e < 2304; e += 256) {
        int oc = e / 48, ic = e % 48;
        float v = pw[e];
        w2s[ic*48 + oc] = pack2(v, v);
    }
    for (int e = tid; e < 48*128; e += 256) {
        int ic = e >> 7, p2 = (e & 127) * 2;
        int head = ic / 6, ci = ic % 6;
        int p = ci*4 + nh;
        const __half* src = g_pre16 +
            ((size_t)(b*HEADS + head)*24 + p) * NPIX * 4 + soff + p2;
        float2 f = __half22float2(*(const __half2*)src);
        *(float2*)&in_s[ic*260 + p2] = f;
    }
    __syncthreads();

    ull acc[6][4];
    #pragma unroll
    for (int i = 0; i < 6; i++)
        #pragma unroll
        for (int u = 0; u < 4; u++) acc[i][u] = 0ull;
    #pragma unroll 4
    for (int ic = 0; ic < 48; ic++) {
        float4 xa = *(const float4*)&in_s[ic*260 + 4*tx];
        float4 xc = *(const float4*)&in_s[ic*260 + 128 + 4*tx];
        ull a0 = pack2(xa.x, xa.y), a1 = pack2(xa.z, xa.w);
        ull a2 = pack2(xc.x, xc.y), a3 = pack2(xc.z, xc.w);
        #pragma unroll
        for (int i = 0; i < 6; i++) {
            ull wv = w2s[ic*48 + ty*6 + i];
            acc[i][0] = fma2(wv, a0, acc[i][0]);
            acc[i][1] = fma2(wv, a1, acc[i][1]);
            acc[i][2] = fma2(wv, a2, acc[i][2]);
            acc[i][3] = fma2(wv, a3, acc[i][3]);
        }
    }
    #pragma unroll
    for (int i = 0; i < 6; i++) {
        int oc = ty*6 + i;
        float* ob = out + ((size_t)(b*CDIM + oc)*512 + h)*512 + wb;
        float2 f0 = unpack2(acc[i][0]), f1 = unpack2(acc[i][1]);
        float2 f2 = unpack2(acc[i][2]), f3 = unpack2(acc[i][3]);
        float4 o0; o0.x = f0.x; o0.y = f0.y; o0.z = f1.x; o0.w = f1.y;
        float4 o1; o1.x = f2.x; o1.y = f2.y; o1.z = f3.x; o1.w = f3.y;
        *(float4*)&ob[4*tx]       = o0;
        *(float4*)&ob[128 + 4*tx] = o1;
    }
}

extern "C" void kernel_launch(void* const* d_in, const int* in_sizes, int n_in,
                              void* d_out, int out_size) {
    const float* x     = (const float*)d_in[0];
    const float* qkvw  = (const float*)d_in[1];
    const float* dww   = (const float*)d_in[2];
    const float* projw = (const float*)d_in[3];
    const float* temp  = (const float*)d_in[4];
    float* out = (float*)d_out;

    cudaFuncSetAttribute(k_pw,   cudaFuncAttributeMaxDynamicSharedMemorySize, PW_SMEM);
    cudaFuncSetAttribute(k_gram, cudaFuncAttributeMaxDynamicSharedMemorySize, GRAM_SMEM);
    cudaFuncSetAttribute(k_av,   cudaFuncAttributeMaxDynamicSharedMemorySize, AV_SMEM);
    cudaFuncSetAttribute(k_proj, cudaFuncAttributeMaxDynamicSharedMemorySize, PROJ_SMEM);

    k_zero<<<576, 256>>>();
    k_pw  <<<dim3(HW/256, BATCH), 256, PW_SMEM>>>(x, qkvw);
    k_dw  <<<BATCH*QC*64, 256>>>(dww);
    k_gram<<<dim3(32, NBH), 256, GRAM_SMEM>>>();
    k_soft<<<192, 256>>>(temp);
    k_av  <<<dim3(NPIX/128, NBH), 256, AV_SMEM>>>();
    k_proj<<<dim3(2, 512, BATCH), dim3(32, 8), PROJ_SMEM>>>(projw, out);
}